// round 15
// baseline (speedup 1.0000x reference)
#include <cuda_runtime.h>

// RateBasedNeuron: N=2^23 neuron sim, warp-autonomous formulation (v10).
//  rate[t] = a*rate[t-1] + alpha*I[t]  (a = 1-1/tau, contractive)
//  p[t] = clip(rate/thr,0,1)*0.1 ; 3-state refractory DFA -> spikes.
//
// Each WARP owns an independent 1536-elem tile + 512-elem halo. 8 serial
// segments of 256; each lane owns 8 consecutive elems (two float4); IIR
// B-scan with constant round multipliers + DFA state-map scan via shuffles,
// scalar carries between segments. DFA per-lane work via 256-entry shared
// LUT (spike masks for 3 incoming states + byte-packed transition map).
//
// v10: (a) double-buffer prefetch RESTORED (v9 showed per-warp latency, not
// warp count, is binding: occ 39->52 but issue 57->49 without it);
// (b) WTILE=1536 kept, __launch_bounds__(256,4) -> 64-reg cap, 32 warps/SM;
// (c) halo segment 0 is IIR-only: u not loaded, e forced 0 (DFA re-warms
// over segment 1's 256 real steps; collapse leaves ~1e-40 risk) -> u read
// traffic -12.5%.

#define WSEG    256
#define NSEG    8
#define WREGION (WSEG * NSEG)        // 2048
#define WHALO   512
#define HSEG    (WHALO / WSEG)       // 2
#define WTILE   (WREGION - WHALO)    // 1536
#define THREADS 256
#define FULLMASK 0xffffffffu

// compose byte-packed 3-state maps: apply g first, then f. h[i] = f[g[i]].
// __byte_perm selector = nibbles -> compress g's bytes into nibbles first.
__device__ __forceinline__ unsigned dfa_compose(unsigned f, unsigned g) {
    unsigned sel = (g & 3u) | ((g >> 4) & 0x30u) | ((g >> 8) & 0x300u);
    return __byte_perm(f, 0, sel);
}

template <bool INTERIOR>
__device__ __forceinline__ void run_warp(
    const float* __restrict__ gI, const float* __restrict__ gU,
    float* __restrict__ gOut, const uint2* __restrict__ tbl,
    long long base, long long N,
    float alpha, float a, float rthr, int lane)
{
    // powers of a: scan round multipliers (lane span = 8 elems)
    const float a2   = a * a;
    const float a4   = a2 * a2;
    const float c1   = a4 * a4;      // a^8
    const float c2   = c1 * c1;      // a^16
    const float c4   = c2 * c2;      // a^32
    const float c8   = c4 * c4;      // a^64
    const float c16  = c8 * c8;      // a^128
    const float cSeg = c16 * c16;    // a^256
    float aL = 1.0f, bp = c1;        // aL = a^{8*lane}
    #pragma unroll
    for (int bit = 0; bit < 5; bit++) {
        if (lane & (1 << bit)) aL *= bp;
        bp *= bp;
    }

    float    rcar = 0.0f;   // IIR carry entering current segment
    unsigned scar = 0u;     // DFA carry state in {0,1,2}

    const float4* pI4 = (const float4*)(gI + base);
    const float4* pU4 = (const float4*)(gU + base);
    float4*       pO4 = (float4*)(gOut + base);
    const int li = 2 * lane;

    float4 nb0, nb1, nu0, nu1;

    if (INTERIOR) {
        // ---- segment 0: IIR-only (no u, e forced 0, spikes discarded) ----
        float4 cb0 = pI4[li], cb1 = pI4[li + 1];
        // prefetch segment 1 (b and u)
        {
            const int nx = (WSEG / 4) + li;
            nb0 = pI4[nx]; nb1 = pI4[nx + 1];
            nu0 = pU4[nx]; nu1 = pU4[nx + 1];
        }
        float B = alpha * cb0.x;
        B = fmaf(B, a, alpha * cb0.y); B = fmaf(B, a, alpha * cb0.z);
        B = fmaf(B, a, alpha * cb0.w); B = fmaf(B, a, alpha * cb1.x);
        B = fmaf(B, a, alpha * cb1.y); B = fmaf(B, a, alpha * cb1.z);
        B = fmaf(B, a, alpha * cb1.w);
        float Bi = B, Bu;
        Bu = __shfl_up_sync(FULLMASK, Bi, 1);  if (lane >= 1)  Bi = fmaf(Bu, c1,  Bi);
        Bu = __shfl_up_sync(FULLMASK, Bi, 2);  if (lane >= 2)  Bi = fmaf(Bu, c2,  Bi);
        Bu = __shfl_up_sync(FULLMASK, Bi, 4);  if (lane >= 4)  Bi = fmaf(Bu, c4,  Bi);
        Bu = __shfl_up_sync(FULLMASK, Bi, 8);  if (lane >= 8)  Bi = fmaf(Bu, c8,  Bi);
        Bu = __shfl_up_sync(FULLMASK, Bi, 16); if (lane >= 16) Bi = fmaf(Bu, c16, Bi);
        rcar = __shfl_sync(FULLMASK, Bi, 31);      // rcar was 0
        // scar stays 0 (re-warmed over segment 1)
    }

    const int seg_lo = INTERIOR ? 1 : 0;
    #pragma unroll 1
    for (int seg = seg_lo; seg < NSEG; seg++) {
        float4 cb0, cb1, cu0, cu1;
        if (INTERIOR) {
            cb0 = nb0; cb1 = nb1; cu0 = nu0; cu1 = nu1;
            if (seg + 1 < NSEG) {                  // prefetch next segment
                const int nx = (seg + 1) * (WSEG / 4) + li;
                nb0 = pI4[nx]; nb1 = pI4[nx + 1];
                nu0 = pU4[nx]; nu1 = pU4[nx + 1];
            }
        } else {
            long long gg = base + (long long)seg * WSEG + lane * 8;
            float tmpb[8], tmpu[8];
            #pragma unroll
            for (int t = 0; t < 8; t++) {
                long long g = gg + t;
                tmpb[t] = (g >= 1 && g < N) ? gI[g] : 0.0f;
                tmpu[t] = (g >= 0 && g < N) ? gU[g] : 1.0f;
            }
            cb0 = make_float4(tmpb[0], tmpb[1], tmpb[2], tmpb[3]);
            cb1 = make_float4(tmpb[4], tmpb[5], tmpb[6], tmpb[7]);
            cu0 = make_float4(tmpu[0], tmpu[1], tmpu[2], tmpu[3]);
            cu1 = make_float4(tmpu[4], tmpu[5], tmpu[6], tmpu[7]);
        }

        const float b0 = alpha * cb0.x, b1 = alpha * cb0.y;
        const float b2 = alpha * cb0.z, b3 = alpha * cb0.w;
        const float b4 = alpha * cb1.x, b5 = alpha * cb1.y;
        const float b6 = alpha * cb1.z, b7 = alpha * cb1.w;

        // ---- lane-local affine reduce (8 elems) ----
        float B = b0;
        B = fmaf(B, a, b1); B = fmaf(B, a, b2); B = fmaf(B, a, b3);
        B = fmaf(B, a, b4); B = fmaf(B, a, b5); B = fmaf(B, a, b6);
        B = fmaf(B, a, b7);

        // ---- warp inclusive B-scan, constant round multipliers ----
        float Bi = B, Bu;
        Bu = __shfl_up_sync(FULLMASK, Bi, 1);  if (lane >= 1)  Bi = fmaf(Bu, c1,  Bi);
        Bu = __shfl_up_sync(FULLMASK, Bi, 2);  if (lane >= 2)  Bi = fmaf(Bu, c2,  Bi);
        Bu = __shfl_up_sync(FULLMASK, Bi, 4);  if (lane >= 4)  Bi = fmaf(Bu, c4,  Bi);
        Bu = __shfl_up_sync(FULLMASK, Bi, 8);  if (lane >= 8)  Bi = fmaf(Bu, c8,  Bi);
        Bu = __shfl_up_sync(FULLMASK, Bi, 16); if (lane >= 16) Bi = fmaf(Bu, c16, Bi);
        float Be  = __shfl_up_sync(FULLMASK, Bi, 1);
        if (lane == 0) Be = 0.0f;
        float B31 = __shfl_sync(FULLMASK, Bi, 31);
        float rin = fmaf(aL, rcar, Be);
        rcar = fmaf(cSeg, rcar, B31);

        // ---- rates -> p -> eligibility bits (r >= 0, fmax elided) ----
        float r = rin, q;
        unsigned e = 0;
        r = fmaf(a, r, b0); q = fminf(r * rthr, 1.0f) * 0.1f; e |= (cu0.x < q ?   1u : 0u);
        r = fmaf(a, r, b1); q = fminf(r * rthr, 1.0f) * 0.1f; e |= (cu0.y < q ?   2u : 0u);
        r = fmaf(a, r, b2); q = fminf(r * rthr, 1.0f) * 0.1f; e |= (cu0.z < q ?   4u : 0u);
        r = fmaf(a, r, b3); q = fminf(r * rthr, 1.0f) * 0.1f; e |= (cu0.w < q ?   8u : 0u);
        r = fmaf(a, r, b4); q = fminf(r * rthr, 1.0f) * 0.1f; e |= (cu1.x < q ?  16u : 0u);
        r = fmaf(a, r, b5); q = fminf(r * rthr, 1.0f) * 0.1f; e |= (cu1.y < q ?  32u : 0u);
        r = fmaf(a, r, b6); q = fminf(r * rthr, 1.0f) * 0.1f; e |= (cu1.z < q ?  64u : 0u);
        r = fmaf(a, r, b7); q = fminf(r * rthr, 1.0f) * 0.1f; e |= (cu1.w < q ? 128u : 0u);

        // ---- DFA via LUT: spike masks (3 states) + byte-packed map ----
        uint2 en = tbl[e];

        // ---- warp scan of state maps (exact compose) ----
        unsigned Fi = en.y;
        #pragma unroll
        for (int d = 1; d < 32; d <<= 1) {
            unsigned Fu = __shfl_up_sync(FULLMASK, Fi, d);
            if (lane >= d) Fi = dfa_compose(Fi, Fu);   // Fu earlier
        }
        unsigned Fe  = __shfl_up_sync(FULLMASK, Fi, 1);
        unsigned F31 = __shfl_sync(FULLMASK, Fi, 31);
        unsigned sin = (lane == 0) ? scar : ((Fe >> (scar << 3)) & 3u);
        scar = (F31 >> (scar << 3)) & 3u;

        unsigned spikes = (en.x >> (sin << 3)) & 0xffu;

        // ---- store (skip halo segments) ----
        if (seg >= HSEG) {
            if (INTERIOR) {
                float4 s0, s1;
                s0.x = (spikes &   1u) ? 1.0f : 0.0f;
                s0.y = (spikes &   2u) ? 1.0f : 0.0f;
                s0.z = (spikes &   4u) ? 1.0f : 0.0f;
                s0.w = (spikes &   8u) ? 1.0f : 0.0f;
                s1.x = (spikes &  16u) ? 1.0f : 0.0f;
                s1.y = (spikes &  32u) ? 1.0f : 0.0f;
                s1.z = (spikes &  64u) ? 1.0f : 0.0f;
                s1.w = (spikes & 128u) ? 1.0f : 0.0f;
                const int ox = seg * (WSEG / 4) + li;
                pO4[ox] = s0; pO4[ox + 1] = s1;
            } else {
                long long gg = base + (long long)seg * WSEG + lane * 8;
                #pragma unroll
                for (int t = 0; t < 8; t++) {
                    long long g = gg + t;
                    if (g >= 0 && g < N)
                        gOut[g] = ((spikes >> t) & 1u) ? 1.0f : 0.0f;
                }
            }
        }
    }
}

__global__ void __launch_bounds__(THREADS, 4)
neuron_kernel(const float* __restrict__ gI, const float* __restrict__ gU,
              const float* __restrict__ gTau, const float* __restrict__ gThr,
              float* __restrict__ gOut, int N, int nWT)
{
    __shared__ uint2 tbl[256];

    // ---- build 8-step refractory-DFA LUT (one entry per thread) ----
    {
        const unsigned e = threadIdx.x;   // THREADS == 256
        unsigned spAll = 0, mAll = 0;
        #pragma unroll
        for (int s0 = 0; s0 < 3; s0++) {
            int s = s0;
            unsigned sp = 0;
            #pragma unroll
            for (int k = 0; k < 8; k++) {
                bool fire = (s == 0) && ((e >> k) & 1u);
                if (fire) sp |= 1u << k;
                s = fire ? 2 : (s > 0 ? s - 1 : 0);
            }
            spAll |= sp << (8 * s0);
            mAll  |= (unsigned)s << (8 * s0);
        }
        tbl[e] = make_uint2(spAll, mAll);
    }
    __syncthreads();

    const int gwarp = (int)((blockIdx.x * blockDim.x + threadIdx.x) >> 5);
    if (gwarp >= nWT) return;                       // whole-warp uniform exit
    const int lane = threadIdx.x & 31;

    const float alpha = __fdiv_rn(1.0f, gTau[0]);
    const float rthr  = __fdiv_rn(1.0f, gThr[0]);
    const float a     = 1.0f - alpha;

    const long long base = (long long)gwarp * WTILE - WHALO;
    const bool interior = (base >= 1) && (base + WREGION <= (long long)N);

    if (interior)
        run_warp<true >(gI, gU, gOut, tbl, base, N, alpha, a, rthr, lane);
    else
        run_warp<false>(gI, gU, gOut, tbl, base, N, alpha, a, rthr, lane);
}

extern "C" void kernel_launch(void* const* d_in, const int* in_sizes, int n_in,
                              void* d_out, int out_size)
{
    const float* I   = (const float*)d_in[0];
    const float* u   = (const float*)d_in[1];
    const float* tau = (const float*)d_in[2];
    const float* thr = (const float*)d_in[3];
    float* out = (float*)d_out;
    const int N = in_sizes[0];

    const int nWT = (N + WTILE - 1) / WTILE;                // 5462 warp tiles
    const int blocks = (nWT * 32 + THREADS - 1) / THREADS;  // 683

    neuron_kernel<<<blocks, THREADS>>>(I, u, tau, thr, out, N, nWT);
}

// round 17
// speedup vs baseline: 1.0057x; 1.0057x over previous
#include <cuda_runtime.h>

// RateBasedNeuron: N=2^23 neuron sim, warp-autonomous formulation (v11).
//  rate[t] = a*rate[t-1] + alpha*I[t]  (a = 1-1/tau, contractive)
//  p[t] = clip(rate/thr,0,1)*0.1 ; 3-state refractory DFA -> spikes.
//
// Each WARP owns 2048-elem tile + 512 halo (= segment pair 0). 10 segments
// of 256 processed as 5 PAIRS: both segments' scan chains (IIR B-scan, DFA
// map scan) are carry-independent, so pairing them in one loop body gives
// ~2x ILP on the latency-bound shuffle/fma chains that v8-v10 showed are
// the binding constraint (issue stuck ~50-57%, occupancy/traffic changes
// neutral). Prefetch: next pair's b one pair ahead; u loaded at pair top.
// DFA per-lane work via 256-entry shared LUT. bounds(256,3): ~84-reg cap.

#define WSEG    256
#define NSEG    10
#define NPAIR   (NSEG / 2)
#define WREGION (WSEG * NSEG)        // 2560
#define WHALO   512
#define HSEG    (WHALO / WSEG)       // 2 (= pair 0)
#define WTILE   (WREGION - WHALO)    // 2048
#define THREADS 256
#define FULLMASK 0xffffffffu

// compose byte-packed 3-state maps: apply g first, then f. h[i] = f[g[i]].
// __byte_perm selector = nibbles -> compress g's bytes into nibbles first.
__device__ __forceinline__ unsigned dfa_compose(unsigned f, unsigned g) {
    unsigned sel = (g & 3u) | ((g >> 4) & 0x30u) | ((g >> 8) & 0x300u);
    return __byte_perm(f, 0, sel);
}

__device__ __forceinline__ void run_interior(
    const float* __restrict__ gI, const float* __restrict__ gU,
    float* __restrict__ gOut, const uint2* __restrict__ tbl,
    long long base, float alpha, float a, float rthr, int lane)
{
    // powers of a (scan round multipliers; lane span = 8)
    const float a2   = a * a;
    const float a4   = a2 * a2;
    const float c1   = a4 * a4;      // a^8
    const float c2   = c1 * c1;      // a^16
    const float c4   = c2 * c2;      // a^32
    const float c8   = c4 * c4;      // a^64
    const float c16  = c8 * c8;      // a^128
    const float cSeg = c16 * c16;    // a^256
    float aL = 1.0f, bp = c1;        // aL = a^{8*lane}
    #pragma unroll
    for (int bit = 0; bit < 5; bit++) {
        if (lane & (1 << bit)) aL *= bp;
        bp *= bp;
    }

    float    rcar = 0.0f;
    unsigned scar = 0u;

    const float4* pI4 = (const float4*)(gI + base);
    const float4* pU4 = (const float4*)(gU + base);
    float4*       pO4 = (float4*)(gOut + base);
    const int li = 2 * lane;

    // prefetch pair 0 b
    float4 nA0 = pI4[li],      nA1 = pI4[li + 1];
    float4 nB0 = pI4[64 + li], nB1 = pI4[64 + li + 1];

    #pragma unroll 1
    for (int p = 0; p < NPAIR; p++) {
        const int ixA = p * 128 + li;

        // u loads for this pair (consumed in epilogue ~250+ cyc later)
        float4 uA0 = pU4[ixA],      uA1 = pU4[ixA + 1];
        float4 uB0 = pU4[ixA + 64], uB1 = pU4[ixA + 65];

        float4 bA0 = nA0, bA1 = nA1, bB0 = nB0, bB1 = nB1;
        if (p + 1 < NPAIR) {         // prefetch next pair's b (1 pair lead)
            const int nx = ixA + 128;
            nA0 = pI4[nx];      nA1 = pI4[nx + 1];
            nB0 = pI4[nx + 64]; nB1 = pI4[nx + 65];
        }

        const float fA0 = alpha * bA0.x, fA1 = alpha * bA0.y;
        const float fA2 = alpha * bA0.z, fA3 = alpha * bA0.w;
        const float fA4 = alpha * bA1.x, fA5 = alpha * bA1.y;
        const float fA6 = alpha * bA1.z, fA7 = alpha * bA1.w;
        const float fB0 = alpha * bB0.x, fB1 = alpha * bB0.y;
        const float fB2 = alpha * bB0.z, fB3 = alpha * bB0.w;
        const float fB4 = alpha * bB1.x, fB5 = alpha * bB1.y;
        const float fB6 = alpha * bB1.z, fB7 = alpha * bB1.w;

        // ---- lane-local reduces (independent chains A | B) ----
        float BA = fA0, BB = fB0;
        BA = fmaf(BA, a, fA1); BB = fmaf(BB, a, fB1);
        BA = fmaf(BA, a, fA2); BB = fmaf(BB, a, fB2);
        BA = fmaf(BA, a, fA3); BB = fmaf(BB, a, fB3);
        BA = fmaf(BA, a, fA4); BB = fmaf(BB, a, fB4);
        BA = fmaf(BA, a, fA5); BB = fmaf(BB, a, fB5);
        BA = fmaf(BA, a, fA6); BB = fmaf(BB, a, fB6);
        BA = fmaf(BA, a, fA7); BB = fmaf(BB, a, fB7);

        // ---- warp B-scans, interleaved ----
        float BiA = BA, BiB = BB, Bt;
        Bt = __shfl_up_sync(FULLMASK, BiA, 1);  if (lane >= 1)  BiA = fmaf(Bt, c1,  BiA);
        Bt = __shfl_up_sync(FULLMASK, BiB, 1);  if (lane >= 1)  BiB = fmaf(Bt, c1,  BiB);
        Bt = __shfl_up_sync(FULLMASK, BiA, 2);  if (lane >= 2)  BiA = fmaf(Bt, c2,  BiA);
        Bt = __shfl_up_sync(FULLMASK, BiB, 2);  if (lane >= 2)  BiB = fmaf(Bt, c2,  BiB);
        Bt = __shfl_up_sync(FULLMASK, BiA, 4);  if (lane >= 4)  BiA = fmaf(Bt, c4,  BiA);
        Bt = __shfl_up_sync(FULLMASK, BiB, 4);  if (lane >= 4)  BiB = fmaf(Bt, c4,  BiB);
        Bt = __shfl_up_sync(FULLMASK, BiA, 8);  if (lane >= 8)  BiA = fmaf(Bt, c8,  BiA);
        Bt = __shfl_up_sync(FULLMASK, BiB, 8);  if (lane >= 8)  BiB = fmaf(Bt, c8,  BiB);
        Bt = __shfl_up_sync(FULLMASK, BiA, 16); if (lane >= 16) BiA = fmaf(Bt, c16, BiA);
        Bt = __shfl_up_sync(FULLMASK, BiB, 16); if (lane >= 16) BiB = fmaf(Bt, c16, BiB);
        float BeA  = __shfl_up_sync(FULLMASK, BiA, 1); if (lane == 0) BeA = 0.0f;
        float B31A = __shfl_sync(FULLMASK, BiA, 31);
        float BeB  = __shfl_up_sync(FULLMASK, BiB, 1); if (lane == 0) BeB = 0.0f;
        float B31B = __shfl_sync(FULLMASK, BiB, 31);

        // ---- carry chain (short): rinB does NOT wait on eligA ----
        float rinA  = fmaf(aL, rcar, BeA);
        float rcarM = fmaf(cSeg, rcar, B31A);
        float rinB  = fmaf(aL, rcarM, BeB);
        rcar        = fmaf(cSeg, rcarM, B31B);

        // ---- eligibility (two independent serial chains) ----
        float rA = rinA, rB = rinB, q;
        unsigned eA = 0, eB = 0;
        rA = fmaf(a, rA, fA0); q = fminf(rA * rthr, 1.0f) * 0.1f; eA |= (uA0.x < q ?   1u : 0u);
        rB = fmaf(a, rB, fB0); q = fminf(rB * rthr, 1.0f) * 0.1f; eB |= (uB0.x < q ?   1u : 0u);
        rA = fmaf(a, rA, fA1); q = fminf(rA * rthr, 1.0f) * 0.1f; eA |= (uA0.y < q ?   2u : 0u);
        rB = fmaf(a, rB, fB1); q = fminf(rB * rthr, 1.0f) * 0.1f; eB |= (uB0.y < q ?   2u : 0u);
        rA = fmaf(a, rA, fA2); q = fminf(rA * rthr, 1.0f) * 0.1f; eA |= (uA0.z < q ?   4u : 0u);
        rB = fmaf(a, rB, fB2); q = fminf(rB * rthr, 1.0f) * 0.1f; eB |= (uB0.z < q ?   4u : 0u);
        rA = fmaf(a, rA, fA3); q = fminf(rA * rthr, 1.0f) * 0.1f; eA |= (uA0.w < q ?   8u : 0u);
        rB = fmaf(a, rB, fB3); q = fminf(rB * rthr, 1.0f) * 0.1f; eB |= (uB0.w < q ?   8u : 0u);
        rA = fmaf(a, rA, fA4); q = fminf(rA * rthr, 1.0f) * 0.1f; eA |= (uA1.x < q ?  16u : 0u);
        rB = fmaf(a, rB, fB4); q = fminf(rB * rthr, 1.0f) * 0.1f; eB |= (uB1.x < q ?  16u : 0u);
        rA = fmaf(a, rA, fA5); q = fminf(rA * rthr, 1.0f) * 0.1f; eA |= (uA1.y < q ?  32u : 0u);
        rB = fmaf(a, rB, fB5); q = fminf(rB * rthr, 1.0f) * 0.1f; eB |= (uB1.y < q ?  32u : 0u);
        rA = fmaf(a, rA, fA6); q = fminf(rA * rthr, 1.0f) * 0.1f; eA |= (uA1.z < q ?  64u : 0u);
        rB = fmaf(a, rB, fB6); q = fminf(rB * rthr, 1.0f) * 0.1f; eB |= (uB1.z < q ?  64u : 0u);
        rA = fmaf(a, rA, fA7); q = fminf(rA * rthr, 1.0f) * 0.1f; eA |= (uA1.w < q ? 128u : 0u);
        rB = fmaf(a, rB, fB7); q = fminf(rB * rthr, 1.0f) * 0.1f; eB |= (uB1.w < q ? 128u : 0u);

        // ---- DFA LUT (both lookups issued together) ----
        uint2 enA = tbl[eA];
        uint2 enB = tbl[eB];

        // ---- DFA map scans, interleaved ----
        unsigned FiA = enA.y, FiB = enB.y, Ft;
        #pragma unroll
        for (int d = 1; d < 32; d <<= 1) {
            Ft = __shfl_up_sync(FULLMASK, FiA, d); if (lane >= d) FiA = dfa_compose(FiA, Ft);
            Ft = __shfl_up_sync(FULLMASK, FiB, d); if (lane >= d) FiB = dfa_compose(FiB, Ft);
        }
        unsigned FeA  = __shfl_up_sync(FULLMASK, FiA, 1);
        unsigned F31A = __shfl_sync(FULLMASK, FiA, 31);
        unsigned FeB  = __shfl_up_sync(FULLMASK, FiB, 1);
        unsigned F31B = __shfl_sync(FULLMASK, FiB, 31);

        unsigned sinA  = (lane == 0) ? scar : ((FeA >> (scar << 3)) & 3u);
        unsigned scarM = (F31A >> (scar << 3)) & 3u;
        unsigned sinB  = (lane == 0) ? scarM : ((FeB >> (scarM << 3)) & 3u);
        scar           = (F31B >> (scarM << 3)) & 3u;

        unsigned spA = (enA.x >> (sinA << 3)) & 0xffu;
        unsigned spB = (enB.x >> (sinB << 3)) & 0xffu;

        // ---- stores (pair 0 = halo, skipped) ----
        if (p >= 1) {
            float4 s;
            s.x = (spA &   1u) ? 1.0f : 0.0f;
            s.y = (spA &   2u) ? 1.0f : 0.0f;
            s.z = (spA &   4u) ? 1.0f : 0.0f;
            s.w = (spA &   8u) ? 1.0f : 0.0f;
            pO4[ixA] = s;
            s.x = (spA &  16u) ? 1.0f : 0.0f;
            s.y = (spA &  32u) ? 1.0f : 0.0f;
            s.z = (spA &  64u) ? 1.0f : 0.0f;
            s.w = (spA & 128u) ? 1.0f : 0.0f;
            pO4[ixA + 1] = s;
            s.x = (spB &   1u) ? 1.0f : 0.0f;
            s.y = (spB &   2u) ? 1.0f : 0.0f;
            s.z = (spB &   4u) ? 1.0f : 0.0f;
            s.w = (spB &   8u) ? 1.0f : 0.0f;
            pO4[ixA + 64] = s;
            s.x = (spB &  16u) ? 1.0f : 0.0f;
            s.y = (spB &  32u) ? 1.0f : 0.0f;
            s.z = (spB &  64u) ? 1.0f : 0.0f;
            s.w = (spB & 128u) ? 1.0f : 0.0f;
            pO4[ixA + 65] = s;
        }
    }
}

// slow guarded path for the 2 edge warp-tiles
__device__ __forceinline__ void run_edge(
    const float* __restrict__ gI, const float* __restrict__ gU,
    float* __restrict__ gOut, const uint2* __restrict__ tbl,
    long long base, long long N,
    float alpha, float a, float rthr, int lane)
{
    const float a2   = a * a;
    const float a4   = a2 * a2;
    const float c1   = a4 * a4;
    const float c2   = c1 * c1;
    const float c4   = c2 * c2;
    const float c8   = c4 * c4;
    const float c16  = c8 * c8;
    const float cSeg = c16 * c16;
    float aL = 1.0f, bp = c1;
    #pragma unroll
    for (int bit = 0; bit < 5; bit++) {
        if (lane & (1 << bit)) aL *= bp;
        bp *= bp;
    }

    float    rcar = 0.0f;
    unsigned scar = 0u;

    #pragma unroll 1
    for (int seg = 0; seg < NSEG; seg++) {
        long long gg = base + (long long)seg * WSEG + lane * 8;
        float fb[8], fu[8];
        #pragma unroll
        for (int t = 0; t < 8; t++) {
            long long g = gg + t;
            fb[t] = (g >= 1 && g < N) ? alpha * gI[g] : 0.0f;
            fu[t] = (g >= 0 && g < N) ? gU[g] : 1.0f;
        }

        float B = fb[0];
        #pragma unroll
        for (int t = 1; t < 8; t++) B = fmaf(B, a, fb[t]);

        float Bi = B, Bt;
        Bt = __shfl_up_sync(FULLMASK, Bi, 1);  if (lane >= 1)  Bi = fmaf(Bt, c1,  Bi);
        Bt = __shfl_up_sync(FULLMASK, Bi, 2);  if (lane >= 2)  Bi = fmaf(Bt, c2,  Bi);
        Bt = __shfl_up_sync(FULLMASK, Bi, 4);  if (lane >= 4)  Bi = fmaf(Bt, c4,  Bi);
        Bt = __shfl_up_sync(FULLMASK, Bi, 8);  if (lane >= 8)  Bi = fmaf(Bt, c8,  Bi);
        Bt = __shfl_up_sync(FULLMASK, Bi, 16); if (lane >= 16) Bi = fmaf(Bt, c16, Bi);
        float Be  = __shfl_up_sync(FULLMASK, Bi, 1); if (lane == 0) Be = 0.0f;
        float B31 = __shfl_sync(FULLMASK, Bi, 31);
        float rin = fmaf(aL, rcar, Be);
        rcar = fmaf(cSeg, rcar, B31);

        float r = rin;
        unsigned e = 0;
        #pragma unroll
        for (int t = 0; t < 8; t++) {
            r = fmaf(a, r, fb[t]);
            float q = fminf(r * rthr, 1.0f) * 0.1f;
            e |= (fu[t] < q ? 1u : 0u) << t;
        }

        uint2 en = tbl[e];
        unsigned Fi = en.y, Ft;
        #pragma unroll
        for (int d = 1; d < 32; d <<= 1) {
            Ft = __shfl_up_sync(FULLMASK, Fi, d);
            if (lane >= d) Fi = dfa_compose(Fi, Ft);
        }
        unsigned Fe  = __shfl_up_sync(FULLMASK, Fi, 1);
        unsigned F31 = __shfl_sync(FULLMASK, Fi, 31);
        unsigned sin = (lane == 0) ? scar : ((Fe >> (scar << 3)) & 3u);
        scar = (F31 >> (scar << 3)) & 3u;
        unsigned spikes = (en.x >> (sin << 3)) & 0xffu;

        if (seg >= HSEG) {
            #pragma unroll
            for (int t = 0; t < 8; t++) {
                long long g = gg + t;
                if (g >= 0 && g < N)
                    gOut[g] = ((spikes >> t) & 1u) ? 1.0f : 0.0f;
            }
        }
    }
}

__global__ void __launch_bounds__(THREADS, 3)
neuron_kernel(const float* __restrict__ gI, const float* __restrict__ gU,
              const float* __restrict__ gTau, const float* __restrict__ gThr,
              float* __restrict__ gOut, int N, int nWT)
{
    __shared__ uint2 tbl[256];

    // ---- build 8-step refractory-DFA LUT (one entry per thread) ----
    {
        const unsigned e = threadIdx.x;   // THREADS == 256
        unsigned spAll = 0, mAll = 0;
        #pragma unroll
        for (int s0 = 0; s0 < 3; s0++) {
            int s = s0;
            unsigned sp = 0;
            #pragma unroll
            for (int k = 0; k < 8; k++) {
                bool fire = (s == 0) && ((e >> k) & 1u);
                if (fire) sp |= 1u << k;
                s = fire ? 2 : (s > 0 ? s - 1 : 0);
            }
            spAll |= sp << (8 * s0);
            mAll  |= (unsigned)s << (8 * s0);
        }
        tbl[e] = make_uint2(spAll, mAll);
    }
    __syncthreads();

    const int gwarp = (int)((blockIdx.x * blockDim.x + threadIdx.x) >> 5);
    if (gwarp >= nWT) return;                       // whole-warp uniform exit
    const int lane = threadIdx.x & 31;

    const float alpha = __fdiv_rn(1.0f, gTau[0]);
    const float rthr  = __fdiv_rn(1.0f, gThr[0]);
    const float a     = 1.0f - alpha;

    const long long base = (long long)gwarp * WTILE - WHALO;
    const bool interior = (base >= 1) && (base + WREGION <= (long long)N);

    if (interior)
        run_interior(gI, gU, gOut, tbl, base, alpha, a, rthr, lane);
    else
        run_edge(gI, gU, gOut, tbl, base, N, alpha, a, rthr, lane);
}

extern "C" void kernel_launch(void* const* d_in, const int* in_sizes, int n_in,
                              void* d_out, int out_size)
{
    const float* I   = (const float*)d_in[0];
    const float* u   = (const float*)d_in[1];
    const float* tau = (const float*)d_in[2];
    const float* thr = (const float*)d_in[3];
    float* out = (float*)d_out;
    const int N = in_sizes[0];

    const int nWT = (N + WTILE - 1) / WTILE;                // 4096 warp tiles
    const int blocks = (nWT * 32 + THREADS - 1) / THREADS;  // 512

    neuron_kernel<<<blocks, THREADS>>>(I, u, tau, thr, out, N, nWT);
}